// round 16
// baseline (speedup 1.0000x reference)
#include <cuda_runtime.h>
#include <cuda_fp16.h>
#include <math.h>
#include <stdint.h>

// ---------------- problem constants ----------------
#define Bq    128
#define Hh    256
#define NN    512     // 2H
#define TKq   400
#define EMBq  128
#define Vq    50000
#define OOVq  10
#define VXq   (Vq + OOVq)
#define NT    391     // ceil(Vq/128) vocab tiles

#define F_INF __int_as_float(0x7f800000)
#define NEG_BIG (-1.0e30f)

// output segment offsets (flattened tuple order)
#define OFF_FINAL 0LL
#define OFF_H    6401280LL                 // B*(V+OOV)
#define OFF_C    (OFF_H  + (long long)Bq*Hh)
#define OFF_CT   (OFF_C  + (long long)Bq*Hh)
#define OFF_ATTN (OFF_CT + (long long)Bq*NN)
#define OFF_PGEN (OFF_ATTN + (long long)Bq*TKq)
#define OFF_COV  (OFF_PGEN + Bq)

// ---------------- scratch (device globals, no allocation) ----------------
__device__ float g_x[Bq * EMBq];
__device__ float g_h1[Bq * Hh];
__device__ float g_c1[Bq * Hh];
__device__ float g_decfea[Bq * NN];
__device__ float g_scores[Bq * TKq];
__device__ float g_attn[Bq * TKq];
__device__ float g_ctp[Bq * 4 * NN];
__device__ float g_ct[Bq * NN];
__device__ float g_pgen[Bq];
__device__ float g_out1[Bq * Hh];
__device__ __half g_out1h[Bq * Hh];
__device__ __half g_w2h[(size_t)Vq * Hh];      // 25.6 MB fp16 W2
__device__ float g_logits[(size_t)Bq * Vq];
__device__ float g_pm[Bq * NT];
__device__ float g_ps[Bq * NT];
__device__ float g_rmax[Bq];
__device__ float g_rsum[Bq];

__device__ __forceinline__ float sigmoidf_(float x) {
    return 1.0f / (1.0f + __expf(-x));
}
__device__ __forceinline__ float tanh_fast(float x) {
    float y;
    asm("tanh.approx.f32 %0, %1;" : "=f"(y) : "f"(x));
    return y;
}
__device__ __forceinline__ uint32_t smem_u32(const void* p) {
    uint32_t a;
    asm("{ .reg .u64 t; cvta.to.shared.u64 t, %1; cvt.u32.u64 %0, t; }"
        : "=r"(a) : "l"(p));
    return a;
}

__device__ __forceinline__ float warpReduceSum(float v) {
    #pragma unroll
    for (int o = 16; o; o >>= 1) v += __shfl_xor_sync(0xffffffffu, v, o);
    return v;
}
__device__ __forceinline__ float warpReduceMax(float v) {
    #pragma unroll
    for (int o = 16; o; o >>= 1) v = fmaxf(v, __shfl_xor_sync(0xffffffffu, v, o));
    return v;
}
__device__ __forceinline__ float blockReduceSum(float v, float* red) {
    int w = threadIdx.x >> 5, l = threadIdx.x & 31;
    int nw = (blockDim.x + 31) >> 5;
    v = warpReduceSum(v);
    if (l == 0) red[w] = v;
    __syncthreads();
    float r = (threadIdx.x < nw) ? red[threadIdx.x] : 0.0f;
    if (w == 0) {
        r = warpReduceSum(r);
        if (l == 0) red[0] = r;
    }
    __syncthreads();
    r = red[0];
    __syncthreads();
    return r;
}
__device__ __forceinline__ float blockReduceMax(float v, float* red) {
    int w = threadIdx.x >> 5, l = threadIdx.x & 31;
    int nw = (blockDim.x + 31) >> 5;
    v = warpReduceMax(v);
    if (l == 0) red[w] = v;
    __syncthreads();
    float r = (threadIdx.x < nw) ? red[threadIdx.x] : -F_INF;
    if (w == 0) {
        r = warpReduceMax(r);
        if (l == 0) red[0] = r;
    }
    __syncthreads();
    r = red[0];
    __syncthreads();
    return r;
}

// ---------------- K: W2 fp32 -> fp16 preconvert ----------------
__global__ __launch_bounds__(256) void k_w2h(const float* __restrict__ W2) {
    size_t i = ((size_t)blockIdx.x * blockDim.x + threadIdx.x) * 4;
    if (i < (size_t)Vq * Hh) {
        float4 v = *(const float4*)(W2 + i);
        __half2 h0 = __float22half2_rn(make_float2(v.x, v.y));
        __half2 h1 = __float22half2_rn(make_float2(v.z, v.w));
        *(uint2*)(g_w2h + i) = make_uint2(*(uint32_t*)&h0, *(uint32_t*)&h1);
    }
}

// ---------------- K1: x = [ct1 | emb[y]] @ Wx^T + bx ----------------
__global__ __launch_bounds__(256) void k_xgemm(
    const int* __restrict__ y, const float* __restrict__ ct1,
    const float* __restrict__ emb, const float* __restrict__ Wx,
    const float* __restrict__ bx) {
    __shared__ float As[32][65];
    __shared__ float Bs[32][33];
    __shared__ int ys[64];
    int n0 = blockIdx.x * 32;
    int m0 = blockIdx.y * 64;
    int tid = threadIdx.x;
    int tidn = tid & 15;
    int tidm = tid >> 4;
    if (tid < 64) ys[tid] = y[m0 + tid];
    float acc[4][2];
    #pragma unroll
    for (int i = 0; i < 4; i++) { acc[i][0] = 0.f; acc[i][1] = 0.f; }
    __syncthreads();

    const int K = NN + EMBq; // 640
    for (int kk = 0; kk < K; kk += 32) {
        #pragma unroll
        for (int it = 0; it < 2; it++) {
            int idx = tid + it * 256;
            int m = idx >> 3;
            int k4 = (idx & 7) * 4;
            float4 a;
            if (kk < NN) a = *(const float4*)(ct1 + (size_t)(m0 + m) * NN + kk + k4);
            else         a = *(const float4*)(emb + (size_t)ys[m] * EMBq + (kk - NN) + k4);
            As[k4 + 0][m] = a.x; As[k4 + 1][m] = a.y;
            As[k4 + 2][m] = a.z; As[k4 + 3][m] = a.w;
        }
        {
            int n = tid >> 3;
            int k4 = (tid & 7) * 4;
            float4 w = *(const float4*)(Wx + (size_t)(n0 + n) * K + kk + k4);
            Bs[k4 + 0][n] = w.x; Bs[k4 + 1][n] = w.y;
            Bs[k4 + 2][n] = w.z; Bs[k4 + 3][n] = w.w;
        }
        __syncthreads();
        #pragma unroll
        for (int k = 0; k < 32; k++) {
            float a[4], bb[2];
            #pragma unroll
            for (int i = 0; i < 4; i++) a[i] = As[k][tidm + 16 * i];
            bb[0] = Bs[k][tidn];
            bb[1] = Bs[k][tidn + 16];
            #pragma unroll
            for (int i = 0; i < 4; i++) {
                acc[i][0] = fmaf(a[i], bb[0], acc[i][0]);
                acc[i][1] = fmaf(a[i], bb[1], acc[i][1]);
            }
        }
        __syncthreads();
    }
    #pragma unroll
    for (int j = 0; j < 2; j++) {
        int n = n0 + tidn + 16 * j;
        float bv = bx[n];
        #pragma unroll
        for (int i = 0; i < 4; i++) {
            int m = m0 + tidm + 16 * i;
            g_x[(size_t)m * EMBq + n] = acc[i][j] + bv;
        }
    }
}

// ---------------- K2: gates GEMM + LSTM fused ----------------
__global__ __launch_bounds__(256) void k_gates_lstm(
    const float* __restrict__ h0, const float* __restrict__ c0,
    const float* __restrict__ w_ih, const float* __restrict__ b_ih,
    const float* __restrict__ w_hh, const float* __restrict__ b_hh,
    float* __restrict__ out, long long out_size) {
    __shared__ float As[32][33];
    __shared__ float Bs[4][32][33];
    int h0t = blockIdx.x * 32;
    int m0 = blockIdx.y * 32;
    int tid = threadIdx.x;
    int tidn = tid & 15;
    int tidm = tid >> 4;
    float acc[4][2][2];
    #pragma unroll
    for (int g = 0; g < 4; g++)
        #pragma unroll
        for (int i = 0; i < 2; i++) { acc[g][i][0] = 0.f; acc[g][i][1] = 0.f; }

    const int K = EMBq + Hh; // 384
    for (int kk = 0; kk < K; kk += 32) {
        {
            int m = tid >> 3;
            int k4 = (tid & 7) * 4;
            float4 a;
            if (kk < EMBq) a = *(const float4*)(g_x + (size_t)(m0 + m) * EMBq + kk + k4);
            else           a = *(const float4*)(h0 + (size_t)(m0 + m) * Hh + (kk - EMBq) + k4);
            As[k4 + 0][m] = a.x; As[k4 + 1][m] = a.y;
            As[k4 + 2][m] = a.z; As[k4 + 3][m] = a.w;
        }
        #pragma unroll
        for (int g = 0; g < 4; g++) {
            int n = tid >> 3;
            int k4 = (tid & 7) * 4;
            int row = g * Hh + h0t + n;
            float4 w;
            if (kk < EMBq) w = *(const float4*)(w_ih + (size_t)row * EMBq + kk + k4);
            else           w = *(const float4*)(w_hh + (size_t)row * Hh + (kk - EMBq) + k4);
            Bs[g][k4 + 0][n] = w.x; Bs[g][k4 + 1][n] = w.y;
            Bs[g][k4 + 2][n] = w.z; Bs[g][k4 + 3][n] = w.w;
        }
        __syncthreads();
        #pragma unroll
        for (int k = 0; k < 32; k++) {
            float a0 = As[k][tidm], a1 = As[k][tidm + 16];
            #pragma unroll
            for (int g = 0; g < 4; g++) {
                float b0 = Bs[g][k][tidn], b1 = Bs[g][k][tidn + 16];
                acc[g][0][0] = fmaf(a0, b0, acc[g][0][0]);
                acc[g][0][1] = fmaf(a0, b1, acc[g][0][1]);
                acc[g][1][0] = fmaf(a1, b0, acc[g][1][0]);
                acc[g][1][1] = fmaf(a1, b1, acc[g][1][1]);
            }
        }
        __syncthreads();
    }
    #pragma unroll
    for (int i = 0; i < 2; i++) {
        #pragma unroll
        for (int j = 0; j < 2; j++) {
            int m = m0 + tidm + 16 * i;
            int h = h0t + tidn + 16 * j;
            float gi = acc[0][i][j] + b_ih[h]            + b_hh[h];
            float gf = acc[1][i][j] + b_ih[Hh + h]       + b_hh[Hh + h];
            float gg = acc[2][i][j] + b_ih[2 * Hh + h]   + b_hh[2 * Hh + h];
            float go = acc[3][i][j] + b_ih[3 * Hh + h]   + b_hh[3 * Hh + h];
            float c1 = sigmoidf_(gf) * c0[(size_t)m * Hh + h] + sigmoidf_(gi) * tanhf(gg);
            float h1 = sigmoidf_(go) * tanhf(c1);
            g_h1[(size_t)m * Hh + h] = h1;
            g_c1[(size_t)m * Hh + h] = c1;
            long long ih = OFF_H + (long long)m * Hh + h;
            long long ic = OFF_C + (long long)m * Hh + h;
            if (ih < out_size) out[ih] = h1;
            if (ic < out_size) out[ic] = c1;
        }
    }
}

// ---------------- generic 2-segment GEMM (decfea, out1[+fp16 mirror]) ----------------
__global__ __launch_bounds__(256) void gemm_seg(
    const float* __restrict__ A1, int lda1, const float* __restrict__ Wg1, int ws1,
    const float* __restrict__ A2, int lda2, const float* __restrict__ Wg2, int ws2,
    int K1, int K2, const float* __restrict__ bias, float* __restrict__ C,
    __half* __restrict__ Ch, int N) {
    __shared__ float As[32][65];
    __shared__ float Bs[32][33];
    int n0 = blockIdx.x * 32;
    int m0 = blockIdx.y * 64;
    int tid = threadIdx.x;
    int tidn = tid & 15;
    int tidm = tid >> 4;
    float acc[4][2];
    #pragma unroll
    for (int i = 0; i < 4; i++) { acc[i][0] = 0.f; acc[i][1] = 0.f; }

    int K = K1 + K2;
    for (int kk = 0; kk < K; kk += 32) {
        const float* Aseg; const float* Wseg; int lda, ws, ko;
        if (kk < K1) { Aseg = A1; Wseg = Wg1; lda = lda1; ws = ws1; ko = kk; }
        else         { Aseg = A2; Wseg = Wg2; lda = lda2; ws = ws2; ko = kk - K1; }
        #pragma unroll
        for (int it = 0; it < 2; it++) {
            int idx = tid + it * 256;
            int m = idx >> 3;
            int k4 = (idx & 7) * 4;
            float4 a = *(const float4*)(Aseg + (size_t)(m0 + m) * lda + ko + k4);
            As[k4 + 0][m] = a.x; As[k4 + 1][m] = a.y;
            As[k4 + 2][m] = a.z; As[k4 + 3][m] = a.w;
        }
        {
            int n = tid >> 3;
            int k4 = (tid & 7) * 4;
            float4 w = *(const float4*)(Wseg + (size_t)(n0 + n) * ws + ko + k4);
            Bs[k4 + 0][n] = w.x; Bs[k4 + 1][n] = w.y;
            Bs[k4 + 2][n] = w.z; Bs[k4 + 3][n] = w.w;
        }
        __syncthreads();
        #pragma unroll
        for (int k = 0; k < 32; k++) {
            float a[4], bb[2];
            #pragma unroll
            for (int i = 0; i < 4; i++) a[i] = As[k][tidm + 16 * i];
            bb[0] = Bs[k][tidn];
            bb[1] = Bs[k][tidn + 16];
            #pragma unroll
            for (int i = 0; i < 4; i++) {
                acc[i][0] = fmaf(a[i], bb[0], acc[i][0]);
                acc[i][1] = fmaf(a[i], bb[1], acc[i][1]);
            }
        }
        __syncthreads();
    }
    #pragma unroll
    for (int j = 0; j < 2; j++) {
        int n = n0 + tidn + 16 * j;
        float bv = bias ? bias[n] : 0.0f;
        #pragma unroll
        for (int i = 0; i < 4; i++) {
            int m = m0 + tidm + 16 * i;
            float v = acc[i][j] + bv;
            C[(size_t)m * N + n] = v;
            if (Ch) Ch[(size_t)m * N + n] = __float2half(v);
        }
    }
}

// ---------------- K4: attention scores (warp per (b,t)) ----------------
__global__ void k_scores(const float* __restrict__ encf, const float* __restrict__ cov,
                         const float* __restrict__ Wc, const float* __restrict__ vw) {
    int gw = (blockIdx.x * blockDim.x + threadIdx.x) >> 5;
    int lane = threadIdx.x & 31;
    if (gw >= Bq * TKq) return;
    int b = gw / TKq;
    float cv = cov[gw];
    const float4* ef = (const float4*)(encf + (size_t)gw * NN);
    const float4* df = (const float4*)(g_decfea + (size_t)b * NN);
    const float4* wc = (const float4*)Wc;
    const float4* vv = (const float4*)vw;
    float acc = 0.0f;
    #pragma unroll
    for (int i = lane; i < NN / 4; i += 32) {
        float4 a = ef[i], d = df[i], w = wc[i], v = vv[i];
        acc += tanh_fast(a.x + d.x + cv * w.x) * v.x;
        acc += tanh_fast(a.y + d.y + cv * w.y) * v.y;
        acc += tanh_fast(a.z + d.z + cv * w.z) * v.z;
        acc += tanh_fast(a.w + d.w + cv * w.w) * v.w;
    }
    acc = warpReduceSum(acc);
    if (lane == 0) g_scores[gw] = acc;
}

// ---------------- K5: fused softmax + coverage + partial c_t ----------------
__global__ void k_ct_part(const float* __restrict__ enc, const float* __restrict__ mask,
                          const float* __restrict__ cov, float* __restrict__ out,
                          long long out_size) {
    int b = blockIdx.x, q = blockIdx.y;
    int t = threadIdx.x; // 512
    __shared__ float at[512];
    __shared__ float red[32];
    float sc = (t < TKq) ? g_scores[b * TKq + t] : -F_INF;
    float mx = blockReduceMax(sc, red);
    float ex = 0.0f;
    if (t < TKq) ex = __expf(sc - mx) * mask[(size_t)b * TKq + t];
    float sum = blockReduceSum(ex, red);
    float a = ex / sum;
    at[t] = a;
    if (q == 0 && t < TKq) {
        g_attn[(size_t)b * TKq + t] = a;
        long long ia = OFF_ATTN + (long long)b * TKq + t;
        if (ia < out_size) out[ia] = a;
        long long icov = OFF_COV + (long long)b * TKq + t;
        if (icov < out_size) out[icov] = cov[(size_t)b * TKq + t] + a;
    }
    __syncthreads();
    const float* e = enc + ((size_t)b * TKq + q * 100) * NN + t;
    float acc = 0.0f;
    #pragma unroll 4
    for (int tt = 0; tt < 100; tt++) acc = fmaf(at[q * 100 + tt], e[(size_t)tt * NN], acc);
    g_ctp[((b << 2) + q) * NN + t] = acc;
}

// ---------------- K7: combine c_t + p_gen ----------------
__global__ void k_ct_pgen(const float* __restrict__ Wpg, const float* __restrict__ bpg,
                          float* __restrict__ out, long long out_size) {
    int b = blockIdx.x;
    int n = threadIdx.x; // 512
    __shared__ float cts[NN];
    __shared__ float red[32];
    float v = g_ctp[((b << 2) + 0) * NN + n] + g_ctp[((b << 2) + 1) * NN + n]
            + g_ctp[((b << 2) + 2) * NN + n] + g_ctp[((b << 2) + 3) * NN + n];
    g_ct[(size_t)b * NN + n] = v;
    long long ic = OFF_CT + (long long)b * NN + n;
    if (ic < out_size) out[ic] = v;
    cts[n] = v;
    __syncthreads();
    float acc = 0.0f;
    for (int j = n; j < 1152; j += 512) {
        float x;
        if (j < 512)       x = cts[j];
        else if (j < 768)  x = g_h1[(size_t)b * Hh + (j - 512)];
        else if (j < 1024) x = g_c1[(size_t)b * Hh + (j - 768)];
        else               x = g_x[(size_t)b * EMBq + (j - 1024)];
        acc = fmaf(x, Wpg[j], acc);
    }
    acc = blockReduceSum(acc, red);
    if (n == 0) {
        float p = sigmoidf_(acc + bpg[0]);
        g_pgen[b] = p;
        long long ip = OFF_PGEN + b;
        if (ip < out_size) out[ip] = p;
    }
}

// ================= fp16 mma m16n8k16 logits GEMM (cp.async dbuf, online stats) =================
#define AROWU 36                      // u32 per smem row
#define STGU  (2 * 128 * AROWU)       // u32 per stage (A+B)
#define LOGITS_SMEM (2 * STGU * 4)    // 73728 bytes

__device__ __forceinline__ void mma_f16(float* c, const uint32_t* a, const uint32_t* b) {
    asm volatile(
        "mma.sync.aligned.m16n8k16.row.col.f32.f16.f16.f32 "
        "{%0,%1,%2,%3}, {%4,%5,%6,%7}, {%8,%9}, {%0,%1,%2,%3};"
        : "+f"(c[0]), "+f"(c[1]), "+f"(c[2]), "+f"(c[3])
        : "r"(a[0]), "r"(a[1]), "r"(a[2]), "r"(a[3]), "r"(b[0]), "r"(b[1]));
}
__device__ __forceinline__ void ldsm_x4(uint32_t* r, uint32_t saddr) {
    asm volatile("ldmatrix.sync.aligned.m8n8.x4.shared.b16 {%0,%1,%2,%3}, [%4];"
        : "=r"(r[0]), "=r"(r[1]), "=r"(r[2]), "=r"(r[3]) : "r"(saddr));
}
__device__ __forceinline__ void ldsm_x2(uint32_t* r, uint32_t saddr) {
    asm volatile("ldmatrix.sync.aligned.m8n8.x2.shared.b16 {%0,%1}, [%2];"
        : "=r"(r[0]), "=r"(r[1]) : "r"(saddr));
}

__global__ __launch_bounds__(256) void k_logits_h(const float* __restrict__ b2v) {
    extern __shared__ uint32_t smu[];
    __shared__ float st_m[128][4];
    __shared__ float st_s[128][4];
    uint32_t base = smem_u32(smu);

    int tid = threadIdx.x;
    int lane = tid & 31, wid = tid >> 5;
    int gid = lane >> 2, tig = lane & 3;
    int n0 = blockIdx.x * 128;
    int m0w = (wid >> 2) * 64;
    int n0w = (wid & 3) * 32;

    int aRow  = lane & 15;
    int aColB = ((lane >> 4) << 3) * 2;
    int bRow  = lane & 7;
    int bColB = ((lane >> 3) & 1) * 16;

    float acc[4][4][4];
    #pragma unroll
    for (int i = 0; i < 4; i++)
        #pragma unroll
        for (int j = 0; j < 4; j++)
            #pragma unroll
            for (int q = 0; q < 4; q++) acc[i][j][q] = 0.0f;

    #define PREF(kc, s) do {                                                      \
        int kkh = (kc) * 64;                                                      \
        uint32_t ab = base + (uint32_t)(s) * STGU * 4u;                           \
        uint32_t bb = ab + 128u * AROWU * 4u;                                     \
        _Pragma("unroll")                                                         \
        for (int it = 0; it < 4; it++) {                                          \
            int idx = tid + it * 256;                                             \
            int row = idx >> 3;                                                   \
            int q   = idx & 7;                                                    \
            const void* sa = (const void*)(g_out1h + (size_t)row * Hh + kkh + q * 8); \
            asm volatile("cp.async.ca.shared.global [%0], [%1], 16;"              \
                :: "r"(ab + (uint32_t)(row * 144 + q * 16)), "l"(sa));            \
            int gn = n0 + row;                                                    \
            int nc = (gn < Vq) ? gn : (Vq - 1);                                   \
            const void* sb = (const void*)(g_w2h + (size_t)nc * Hh + kkh + q * 8);\
            asm volatile("cp.async.ca.shared.global [%0], [%1], 16;"              \
                :: "r"(bb + (uint32_t)(row * 144 + q * 16)), "l"(sb));            \
        }                                                                         \
        asm volatile("cp.async.commit_group;");                                   \
    } while (0)

    PREF(0, 0);
    #pragma unroll 1
    for (int kc = 0; kc < 4; kc++) {
        if (kc < 3) {
            PREF(kc + 1, (kc + 1) & 1);
            asm volatile("cp.async.wait_group 1;");
        } else {
            asm volatile("cp.async.wait_group 0;");
        }
        __syncthreads();
        uint32_t asBase = base + (uint32_t)(kc & 1) * STGU * 4u;
        uint32_t bsBase = asBase + 128u * AROWU * 4u;
        #pragma unroll
        for (int ks = 0; ks < 4; ks++) {
            int koB = ks * 32;
            uint32_t a[4][4], b[4][2];
            #pragma unroll
            for (int i = 0; i < 4; i++)
                ldsm_x4(a[i], asBase + (uint32_t)((m0w + i * 16 + aRow) * 144 + koB + aColB));
            #pragma unroll
            for (int j = 0; j < 4; j++)
                ldsm_x2(b[j], bsBase + (uint32_t)((n0w + j * 8 + bRow) * 144 + koB + bColB));
            #pragma unroll
            for (int i = 0; i < 4; i++)
                #pragma unroll
                for (int j = 0; j < 4; j++) mma_f16(acc[i][j], a[i], b[j]);
        }
        __syncthreads();
    }
    #undef PREF

    // epilogue: bias + store logits + per-(row,tile) online softmax partials
    float rm[4][2], rs[4][2];
    #pragma unroll
    for (int i = 0; i < 4; i++) { rm[i][0] = rm[i][1] = NEG_BIG; rs[i][0] = rs[i][1] = 0.f; }

    #pragma unroll
    for (int j = 0; j < 4; j++) {
        int col = n0 + n0w + j * 8 + tig * 2;
        bool valid = (col < Vq);
        float bx0 = 0.f, bx1 = 0.f;
        if (valid) { bx0 = b2v[col]; bx1 = b2v[col + 1]; }
        #pragma unroll
        for (int i = 0; i < 4; i++) {
            float v0 = acc[i][j][0] + bx0, v1 = acc[i][j][1] + bx1;
            float v2 = acc[i][j][2] + bx0, v3 = acc[i][j][3] + bx1;
            if (valid) {
                int r0 = m0w + i * 16 + gid;
                *(float2*)(g_logits + (size_t)r0 * Vq + col) = make_float2(v0, v1);
                *(float2*)(g_logits + (size_t)(r0 + 8) * Vq + col) = make_float2(v2, v3);
                float mp = fmaxf(v0, v1);
                float sp = __expf(v0 - mp) + __expf(v1 - mp);
                float mn = fmaxf(rm[i][0], mp);
                rs[i][0] = rs[i][0] * __expf(rm[i][0] - mn) + sp * __expf(mp - mn);
                rm[i][0] = mn;
                mp = fmaxf(v2, v3);
                sp = __expf(v2 - mp) + __expf(v3 - mp);
                mn = fmaxf(rm[i][1], mp);
                rs[i][1] = rs[i][1] * __expf(rm[i][1] - mn) + sp * __expf(mp - mn);
                rm[i][1] = mn;
            }
        }
    }
    #pragma unroll
    for (int i = 0; i < 4; i++) {
        #pragma unroll
        for (int hf = 0; hf < 2; hf++) {
            float m = rm[i][hf], s = rs[i][hf];
            #pragma unroll
            for (int o = 1; o <= 2; o <<= 1) {
                float m2 = __shfl_xor_sync(0xffffffffu, m, o);
                float s2 = __shfl_xor_sync(0xffffffffu, s, o);
                float mn = fmaxf(m, m2);
                s = s * __expf(m - mn) + s2 * __expf(m2 - mn);
                m = mn;
            }
            rm[i][hf] = m; rs[i][hf] = s;
        }
    }
    int wn = wid & 3;
    if (tig == 0) {
        #pragma unroll
        for (int i = 0; i < 4; i++) {
            #pragma unroll
            for (int hf = 0; hf < 2; hf++) {
                int row = m0w + i * 16 + gid + hf * 8;
                st_m[row][wn] = rm[i][hf];
                st_s[row][wn] = rs[i][hf];
            }
        }
    }
    __syncthreads();
    if (tid < 128) {
        float M = st_m[tid][0], S = st_s[tid][0];
        #pragma unroll
        for (int i = 1; i < 4; i++) {
            float m2 = st_m[tid][i], s2 = st_s[tid][i];
            float mn = fmaxf(M, m2);
            S = S * __expf(M - mn) + s2 * __expf(m2 - mn);
            M = mn;
        }
        g_pm[(size_t)tid * NT + blockIdx.x] = M;
        g_ps[(size_t)tid * NT + blockIdx.x] = S;
    }
}

// ---------------- merge per-tile stats -> per-row (M, S) ----------------
__global__ void k_vmerge() {
    int b = blockIdx.x;
    int tid = threadIdx.x; // 128
    float m = NEG_BIG, s = 0.0f;
    for (int t = tid; t < NT; t += 128) {
        float m2 = g_pm[(size_t)b * NT + t], s2 = g_ps[(size_t)b * NT + t];
        float mn = fmaxf(m, m2);
        s = s * __expf(m - mn) + s2 * __expf(m2 - mn);
        m = mn;
    }
    #pragma unroll
    for (int o = 16; o; o >>= 1) {
        float m2 = __shfl_xor_sync(0xffffffffu, m, o);
        float s2 = __shfl_xor_sync(0xffffffffu, s, o);
        float mn = fmaxf(m, m2);
        s = s * __expf(m - mn) + s2 * __expf(m2 - mn);
        m = mn;
    }
    __shared__ float sm_[4], ss_[4];
    int w = tid >> 5, l = tid & 31;
    if (l == 0) { sm_[w] = m; ss_[w] = s; }
    __syncthreads();
    if (tid == 0) {
        float M = sm_[0], S = ss_[0];
        #pragma unroll
        for (int i = 1; i < 4; i++) {
            float mn = fmaxf(M, sm_[i]);
            S = S * __expf(M - mn) + ss_[i] * __expf(sm_[i] - mn);
            M = mn;
        }
        g_rmax[b] = M;
        g_rsum[b] = S;
    }
}

// ---------------- final dist base ----------------
__global__ void k_final(float* __restrict__ out, long long out_size) {
    int v = blockIdx.x * blockDim.x + threadIdx.x;
    int b = blockIdx.y;
    if (v >= VXq) return;
    float val = 0.0f;
    if (v < Vq)
        val = g_pgen[b] * __expf(g_logits[(size_t)b * Vq + v] - g_rmax[b]) / g_rsum[b];
    long long idx = OFF_FINAL + (long long)b * VXq + v;
    if (idx < out_size) out[idx] = val;
}

// ---------------- copy scatter-add ----------------
__global__ void k_scatter(const int* __restrict__ ebev, float* __restrict__ out,
                          long long out_size) {
    int i = blockIdx.x * blockDim.x + threadIdx.x;
    if (i >= Bq * TKq) return;
    int b = i / TKq;
    float add = (1.0f - g_pgen[b]) * g_attn[i];
    int tgt = ebev[i];
    long long idx = OFF_FINAL + (long long)b * VXq + tgt;
    if (idx < out_size && tgt >= 0 && tgt < VXq) atomicAdd(&out[idx], add);
}

// ---------------- launch ----------------
extern "C" void kernel_launch(void* const* d_in, const int* in_sizes, int n_in,
                              void* d_out, int out_size) {
    const int*   y        = (const int*)  d_in[0];
    const float* s_h      = (const float*)d_in[1];
    const float* s_c      = (const float*)d_in[2];
    const float* enc_out  = (const float*)d_in[3];
    const float* enc_feat = (const float*)d_in[4];
    const float* mask     = (const float*)d_in[5];
    const float* ct1      = (const float*)d_in[6];
    const int*   ebev     = (const int*)  d_in[8];
    const float* cov      = (const float*)d_in[9];
    const float* emb      = (const float*)d_in[11];
    const float* Wx       = (const float*)d_in[12];
    const float* bx       = (const float*)d_in[13];
    const float* w_ih     = (const float*)d_in[14];
    const float* b_ih     = (const float*)d_in[15];
    const float* w_hh     = (const float*)d_in[16];
    const float* b_hh     = (const float*)d_in[17];
    const float* Wp       = (const float*)d_in[18];
    const float* bp       = (const float*)d_in[19];
    const float* v_w      = (const float*)d_in[20];
    const float* Wc       = (const float*)d_in[21];
    const float* Wpg      = (const float*)d_in[22];
    const float* bpg      = (const float*)d_in[23];
    const float* W1       = (const float*)d_in[24];
    const float* b1       = (const float*)d_in[25];
    const float* W2       = (const float*)d_in[26];
    const float* b2       = (const float*)d_in[27];
    float* out = (float*)d_out;
    long long osz = (long long)out_size;

    float*  pg_h1;     cudaGetSymbolAddress((void**)&pg_h1, g_h1);
    float*  pg_c1;     cudaGetSymbolAddress((void**)&pg_c1, g_c1);
    float*  pg_decfea; cudaGetSymbolAddress((void**)&pg_decfea, g_decfea);
    float*  pg_ct;     cudaGetSymbolAddress((void**)&pg_ct, g_ct);
    float*  pg_out1;   cudaGetSymbolAddress((void**)&pg_out1, g_out1);
    __half* pg_out1h;  cudaGetSymbolAddress((void**)&pg_out1h, g_out1h);

    // one-time setup (runs during the uncaptured correctness call)
    static cudaStream_t s2 = nullptr;
    static cudaEvent_t evA = nullptr, evB = nullptr;
    if (!s2) {
        cudaStreamCreateWithFlags(&s2, cudaStreamNonBlocking);
        cudaEventCreateWithFlags(&evA, cudaEventDisableTiming);
        cudaEventCreateWithFlags(&evB, cudaEventDisableTiming);
        cudaFuncSetAttribute(k_logits_h, cudaFuncAttributeMaxDynamicSharedMemorySize,
                             LOGITS_SMEM);
    }

    // fork: W2 fp16 preconvert on side stream, overlapped with attention chain
    cudaEventRecord(evA, 0);
    cudaStreamWaitEvent(s2, evA, 0);
    k_w2h<<<((size_t)Vq * Hh / 4 + 255) / 256, 256, 0, s2>>>(W2);
    cudaEventRecord(evB, s2);

    // main chain (default stream)
    k_xgemm<<<dim3(EMBq / 32, 2), 256>>>(y, ct1, emb, Wx, bx);
    k_gates_lstm<<<dim3(Hh / 32, 4), 256>>>(s_h, s_c, w_ih, b_ih, w_hh, b_hh, out, osz);
    gemm_seg<<<dim3(NN / 32, 2), 256>>>(pg_h1, Hh, Wp, NN,
                                        pg_c1, Hh, Wp + Hh, NN,
                                        Hh, Hh, bp, pg_decfea, (__half*)nullptr, NN);
    k_scores<<<(Bq * TKq) / 8, 256>>>(enc_feat, cov, Wc, v_w);
    k_ct_part<<<dim3(Bq, 4), 512>>>(enc_out, mask, cov, out, osz);
    k_ct_pgen<<<Bq, 512>>>(Wpg, bpg, out, osz);
    gemm_seg<<<dim3(Hh / 32, 2), 256>>>(pg_h1, Hh, W1, Hh + NN,
                                        pg_ct, NN, W1 + Hh, Hh + NN,
                                        Hh, NN, b1, pg_out1, pg_out1h, Hh);

    // join: logits GEMM needs g_w2h
    cudaStreamWaitEvent(0, evB, 0);
    k_logits_h<<<NT, 256, LOGITS_SMEM>>>(b2);
    k_vmerge<<<Bq, 128>>>();
    dim3 gf((VXq + 511) / 512, Bq);
    k_final<<<gf, 512>>>(out, osz);
    k_scatter<<<(Bq * TKq + 255) / 256, 256>>>(ebev, out, osz);
}

// round 17
// speedup vs baseline: 1.4019x; 1.4019x over previous
#include <cuda_runtime.h>
#include <cuda_fp16.h>
#include <math.h>
#include <stdint.h>

// ---------------- problem constants ----------------
#define Bq    128
#define Hh    256
#define NN    512     // 2H
#define TKq   400
#define EMBq  128
#define Vq    50000
#define OOVq  10
#define VXq   (Vq + OOVq)
#define NT    391     // ceil(Vq/128) vocab tiles

#define F_INF __int_as_float(0x7f800000)
#define NEG_BIG (-1.0e30f)

// output segment offsets (flattened tuple order)
#define OFF_FINAL 0LL
#define OFF_H    6401280LL                 // B*(V+OOV)
#define OFF_C    (OFF_H  + (long long)Bq*Hh)
#define OFF_CT   (OFF_C  + (long long)Bq*Hh)
#define OFF_ATTN (OFF_CT + (long long)Bq*NN)
#define OFF_PGEN (OFF_ATTN + (long long)Bq*TKq)
#define OFF_COV  (OFF_PGEN + Bq)

// ---------------- scratch (device globals, no allocation) ----------------
__device__ float g_x[Bq * EMBq];
__device__ float g_h1[Bq * Hh];
__device__ float g_c1[Bq * Hh];
__device__ float g_decfea[Bq * NN];
__device__ float g_scores[Bq * TKq];
__device__ float g_attn[Bq * TKq];
__device__ float g_ctp[Bq * 4 * NN];
__device__ float g_ct[Bq * NN];
__device__ float g_pgen[Bq];
__device__ float g_out1[Bq * Hh];
__device__ __half g_out1h[Bq * Hh];
__device__ __half g_w2h[(size_t)Vq * Hh];      // 25.6 MB fp16 W2
__device__ float g_logits[(size_t)Bq * Vq];
__device__ float g_pm[Bq * NT];
__device__ float g_ps[Bq * NT];
__device__ float g_rmax[Bq];
__device__ float g_rsum[Bq];

__device__ __forceinline__ float sigmoidf_(float x) {
    return 1.0f / (1.0f + __expf(-x));
}
__device__ __forceinline__ float tanh_fast(float x) {
    float y;
    asm("tanh.approx.f32 %0, %1;" : "=f"(y) : "f"(x));
    return y;
}
__device__ __forceinline__ uint32_t smem_u32(const void* p) {
    uint32_t a;
    asm("{ .reg .u64 t; cvta.to.shared.u64 t, %1; cvt.u32.u64 %0, t; }"
        : "=r"(a) : "l"(p));
    return a;
}

__device__ __forceinline__ float warpReduceSum(float v) {
    #pragma unroll
    for (int o = 16; o; o >>= 1) v += __shfl_xor_sync(0xffffffffu, v, o);
    return v;
}
__device__ __forceinline__ float warpReduceMax(float v) {
    #pragma unroll
    for (int o = 16; o; o >>= 1) v = fmaxf(v, __shfl_xor_sync(0xffffffffu, v, o));
    return v;
}
__device__ __forceinline__ float blockReduceSum(float v, float* red) {
    int w = threadIdx.x >> 5, l = threadIdx.x & 31;
    int nw = (blockDim.x + 31) >> 5;
    v = warpReduceSum(v);
    if (l == 0) red[w] = v;
    __syncthreads();
    float r = (threadIdx.x < nw) ? red[threadIdx.x] : 0.0f;
    if (w == 0) {
        r = warpReduceSum(r);
        if (l == 0) red[0] = r;
    }
    __syncthreads();
    r = red[0];
    __syncthreads();
    return r;
}
__device__ __forceinline__ float blockReduceMax(float v, float* red) {
    int w = threadIdx.x >> 5, l = threadIdx.x & 31;
    int nw = (blockDim.x + 31) >> 5;
    v = warpReduceMax(v);
    if (l == 0) red[w] = v;
    __syncthreads();
    float r = (threadIdx.x < nw) ? red[threadIdx.x] : -F_INF;
    if (w == 0) {
        r = warpReduceMax(r);
        if (l == 0) red[0] = r;
    }
    __syncthreads();
    r = red[0];
    __syncthreads();
    return r;
}

// ---------------- K: W2 fp32 -> fp16 preconvert ----------------
__global__ __launch_bounds__(256) void k_w2h(const float* __restrict__ W2) {
    size_t i = ((size_t)blockIdx.x * blockDim.x + threadIdx.x) * 4;
    if (i < (size_t)Vq * Hh) {
        float4 v = *(const float4*)(W2 + i);
        __half2 h0 = __float22half2_rn(make_float2(v.x, v.y));
        __half2 h1 = __float22half2_rn(make_float2(v.z, v.w));
        *(uint2*)(g_w2h + i) = make_uint2(*(uint32_t*)&h0, *(uint32_t*)&h1);
    }
}

// ---------------- K1: x = [ct1 | emb[y]] @ Wx^T + bx ----------------
__global__ __launch_bounds__(256) void k_xgemm(
    const int* __restrict__ y, const float* __restrict__ ct1,
    const float* __restrict__ emb, const float* __restrict__ Wx,
    const float* __restrict__ bx) {
    __shared__ float As[32][65];
    __shared__ float Bs[32][33];
    __shared__ int ys[64];
    int n0 = blockIdx.x * 32;
    int m0 = blockIdx.y * 64;
    int tid = threadIdx.x;
    int tidn = tid & 15;
    int tidm = tid >> 4;
    if (tid < 64) ys[tid] = y[m0 + tid];
    float acc[4][2];
    #pragma unroll
    for (int i = 0; i < 4; i++) { acc[i][0] = 0.f; acc[i][1] = 0.f; }
    __syncthreads();

    const int K = NN + EMBq; // 640
    for (int kk = 0; kk < K; kk += 32) {
        #pragma unroll
        for (int it = 0; it < 2; it++) {
            int idx = tid + it * 256;
            int m = idx >> 3;
            int k4 = (idx & 7) * 4;
            float4 a;
            if (kk < NN) a = *(const float4*)(ct1 + (size_t)(m0 + m) * NN + kk + k4);
            else         a = *(const float4*)(emb + (size_t)ys[m] * EMBq + (kk - NN) + k4);
            As[k4 + 0][m] = a.x; As[k4 + 1][m] = a.y;
            As[k4 + 2][m] = a.z; As[k4 + 3][m] = a.w;
        }
        {
            int n = tid >> 3;
            int k4 = (tid & 7) * 4;
            float4 w = *(const float4*)(Wx + (size_t)(n0 + n) * K + kk + k4);
            Bs[k4 + 0][n] = w.x; Bs[k4 + 1][n] = w.y;
            Bs[k4 + 2][n] = w.z; Bs[k4 + 3][n] = w.w;
        }
        __syncthreads();
        #pragma unroll
        for (int k = 0; k < 32; k++) {
            float a[4], bb[2];
            #pragma unroll
            for (int i = 0; i < 4; i++) a[i] = As[k][tidm + 16 * i];
            bb[0] = Bs[k][tidn];
            bb[1] = Bs[k][tidn + 16];
            #pragma unroll
            for (int i = 0; i < 4; i++) {
                acc[i][0] = fmaf(a[i], bb[0], acc[i][0]);
                acc[i][1] = fmaf(a[i], bb[1], acc[i][1]);
            }
        }
        __syncthreads();
    }
    #pragma unroll
    for (int j = 0; j < 2; j++) {
        int n = n0 + tidn + 16 * j;
        float bv = bx[n];
        #pragma unroll
        for (int i = 0; i < 4; i++) {
            int m = m0 + tidm + 16 * i;
            g_x[(size_t)m * EMBq + n] = acc[i][j] + bv;
        }
    }
}

// ---------------- K2: gates GEMM + LSTM fused ----------------
__global__ __launch_bounds__(256) void k_gates_lstm(
    const float* __restrict__ h0, const float* __restrict__ c0,
    const float* __restrict__ w_ih, const float* __restrict__ b_ih,
    const float* __restrict__ w_hh, const float* __restrict__ b_hh,
    float* __restrict__ out, long long out_size) {
    __shared__ float As[32][33];
    __shared__ float Bs[4][32][33];
    int h0t = blockIdx.x * 32;
    int m0 = blockIdx.y * 32;
    int tid = threadIdx.x;
    int tidn = tid & 15;
    int tidm = tid >> 4;
    float acc[4][2][2];
    #pragma unroll
    for (int g = 0; g < 4; g++)
        #pragma unroll
        for (int i = 0; i < 2; i++) { acc[g][i][0] = 0.f; acc[g][i][1] = 0.f; }

    const int K = EMBq + Hh; // 384
    for (int kk = 0; kk < K; kk += 32) {
        {
            int m = tid >> 3;
            int k4 = (tid & 7) * 4;
            float4 a;
            if (kk < EMBq) a = *(const float4*)(g_x + (size_t)(m0 + m) * EMBq + kk + k4);
            else           a = *(const float4*)(h0 + (size_t)(m0 + m) * Hh + (kk - EMBq) + k4);
            As[k4 + 0][m] = a.x; As[k4 + 1][m] = a.y;
            As[k4 + 2][m] = a.z; As[k4 + 3][m] = a.w;
        }
        #pragma unroll
        for (int g = 0; g < 4; g++) {
            int n = tid >> 3;
            int k4 = (tid & 7) * 4;
            int row = g * Hh + h0t + n;
            float4 w;
            if (kk < EMBq) w = *(const float4*)(w_ih + (size_t)row * EMBq + kk + k4);
            else           w = *(const float4*)(w_hh + (size_t)row * Hh + (kk - EMBq) + k4);
            Bs[g][k4 + 0][n] = w.x; Bs[g][k4 + 1][n] = w.y;
            Bs[g][k4 + 2][n] = w.z; Bs[g][k4 + 3][n] = w.w;
        }
        __syncthreads();
        #pragma unroll
        for (int k = 0; k < 32; k++) {
            float a0 = As[k][tidm], a1 = As[k][tidm + 16];
            #pragma unroll
            for (int g = 0; g < 4; g++) {
                float b0 = Bs[g][k][tidn], b1 = Bs[g][k][tidn + 16];
                acc[g][0][0] = fmaf(a0, b0, acc[g][0][0]);
                acc[g][0][1] = fmaf(a0, b1, acc[g][0][1]);
                acc[g][1][0] = fmaf(a1, b0, acc[g][1][0]);
                acc[g][1][1] = fmaf(a1, b1, acc[g][1][1]);
            }
        }
        __syncthreads();
    }
    #pragma unroll
    for (int i = 0; i < 2; i++) {
        #pragma unroll
        for (int j = 0; j < 2; j++) {
            int m = m0 + tidm + 16 * i;
            int h = h0t + tidn + 16 * j;
            float gi = acc[0][i][j] + b_ih[h]            + b_hh[h];
            float gf = acc[1][i][j] + b_ih[Hh + h]       + b_hh[Hh + h];
            float gg = acc[2][i][j] + b_ih[2 * Hh + h]   + b_hh[2 * Hh + h];
            float go = acc[3][i][j] + b_ih[3 * Hh + h]   + b_hh[3 * Hh + h];
            float c1 = sigmoidf_(gf) * c0[(size_t)m * Hh + h] + sigmoidf_(gi) * tanhf(gg);
            float h1 = sigmoidf_(go) * tanhf(c1);
            g_h1[(size_t)m * Hh + h] = h1;
            g_c1[(size_t)m * Hh + h] = c1;
            long long ih = OFF_H + (long long)m * Hh + h;
            long long ic = OFF_C + (long long)m * Hh + h;
            if (ih < out_size) out[ih] = h1;
            if (ic < out_size) out[ic] = c1;
        }
    }
}

// ---------------- generic 2-segment GEMM (decfea, out1[+fp16 mirror]) ----------------
__global__ __launch_bounds__(256) void gemm_seg(
    const float* __restrict__ A1, int lda1, const float* __restrict__ Wg1, int ws1,
    const float* __restrict__ A2, int lda2, const float* __restrict__ Wg2, int ws2,
    int K1, int K2, const float* __restrict__ bias, float* __restrict__ C,
    __half* __restrict__ Ch, int N) {
    __shared__ float As[32][65];
    __shared__ float Bs[32][33];
    int n0 = blockIdx.x * 32;
    int m0 = blockIdx.y * 64;
    int tid = threadIdx.x;
    int tidn = tid & 15;
    int tidm = tid >> 4;
    float acc[4][2];
    #pragma unroll
    for (int i = 0; i < 4; i++) { acc[i][0] = 0.f; acc[i][1] = 0.f; }

    int K = K1 + K2;
    for (int kk = 0; kk < K; kk += 32) {
        const float* Aseg; const float* Wseg; int lda, ws, ko;
        if (kk < K1) { Aseg = A1; Wseg = Wg1; lda = lda1; ws = ws1; ko = kk; }
        else         { Aseg = A2; Wseg = Wg2; lda = lda2; ws = ws2; ko = kk - K1; }
        #pragma unroll
        for (int it = 0; it < 2; it++) {
            int idx = tid + it * 256;
            int m = idx >> 3;
            int k4 = (idx & 7) * 4;
            float4 a = *(const float4*)(Aseg + (size_t)(m0 + m) * lda + ko + k4);
            As[k4 + 0][m] = a.x; As[k4 + 1][m] = a.y;
            As[k4 + 2][m] = a.z; As[k4 + 3][m] = a.w;
        }
        {
            int n = tid >> 3;
            int k4 = (tid & 7) * 4;
            float4 w = *(const float4*)(Wseg + (size_t)(n0 + n) * ws + ko + k4);
            Bs[k4 + 0][n] = w.x; Bs[k4 + 1][n] = w.y;
            Bs[k4 + 2][n] = w.z; Bs[k4 + 3][n] = w.w;
        }
        __syncthreads();
        #pragma unroll
        for (int k = 0; k < 32; k++) {
            float a[4], bb[2];
            #pragma unroll
            for (int i = 0; i < 4; i++) a[i] = As[k][tidm + 16 * i];
            bb[0] = Bs[k][tidn];
            bb[1] = Bs[k][tidn + 16];
            #pragma unroll
            for (int i = 0; i < 4; i++) {
                acc[i][0] = fmaf(a[i], bb[0], acc[i][0]);
                acc[i][1] = fmaf(a[i], bb[1], acc[i][1]);
            }
        }
        __syncthreads();
    }
    #pragma unroll
    for (int j = 0; j < 2; j++) {
        int n = n0 + tidn + 16 * j;
        float bv = bias ? bias[n] : 0.0f;
        #pragma unroll
        for (int i = 0; i < 4; i++) {
            int m = m0 + tidm + 16 * i;
            float v = acc[i][j] + bv;
            C[(size_t)m * N + n] = v;
            if (Ch) Ch[(size_t)m * N + n] = __float2half(v);
        }
    }
}

// ---------------- K4: attention scores (warp per (b,t), MLP=4 prefetch) ----------------
__global__ void k_scores(const float* __restrict__ encf, const float* __restrict__ cov,
                         const float* __restrict__ Wc, const float* __restrict__ vw) {
    int gw = (blockIdx.x * blockDim.x + threadIdx.x) >> 5;
    int lane = threadIdx.x & 31;
    if (gw >= Bq * TKq) return;
    int b = gw / TKq;
    float cv = cov[gw];
    const float4* ef = (const float4*)(encf + (size_t)gw * NN);
    const float4* df = (const float4*)(g_decfea + (size_t)b * NN);
    const float4* wc = (const float4*)Wc;
    const float4* vv = (const float4*)vw;
    // issue all 4 DRAM loads back-to-back (MLP=4), then overlap the rest
    float4 a0 = ef[lane];
    float4 a1 = ef[lane + 32];
    float4 a2 = ef[lane + 64];
    float4 a3 = ef[lane + 96];
    float4 d0 = df[lane],      w0 = wc[lane],      v0 = vv[lane];
    float4 d1 = df[lane + 32], w1 = wc[lane + 32], v1 = vv[lane + 32];
    float4 d2 = df[lane + 64], w2 = wc[lane + 64], v2 = vv[lane + 64];
    float4 d3 = df[lane + 96], w3 = wc[lane + 96], v3 = vv[lane + 96];
    float acc = 0.0f;
    acc += tanh_fast(a0.x + d0.x + cv * w0.x) * v0.x;
    acc += tanh_fast(a0.y + d0.y + cv * w0.y) * v0.y;
    acc += tanh_fast(a0.z + d0.z + cv * w0.z) * v0.z;
    acc += tanh_fast(a0.w + d0.w + cv * w0.w) * v0.w;
    acc += tanh_fast(a1.x + d1.x + cv * w1.x) * v1.x;
    acc += tanh_fast(a1.y + d1.y + cv * w1.y) * v1.y;
    acc += tanh_fast(a1.z + d1.z + cv * w1.z) * v1.z;
    acc += tanh_fast(a1.w + d1.w + cv * w1.w) * v1.w;
    acc += tanh_fast(a2.x + d2.x + cv * w2.x) * v2.x;
    acc += tanh_fast(a2.y + d2.y + cv * w2.y) * v2.y;
    acc += tanh_fast(a2.z + d2.z + cv * w2.z) * v2.z;
    acc += tanh_fast(a2.w + d2.w + cv * w2.w) * v2.w;
    acc += tanh_fast(a3.x + d3.x + cv * w3.x) * v3.x;
    acc += tanh_fast(a3.y + d3.y + cv * w3.y) * v3.y;
    acc += tanh_fast(a3.z + d3.z + cv * w3.z) * v3.z;
    acc += tanh_fast(a3.w + d3.w + cv * w3.w) * v3.w;
    acc = warpReduceSum(acc);
    if (lane == 0) g_scores[gw] = acc;
}

// ---------------- K5: fused softmax + coverage + partial c_t (MLP=10 groups) ----------------
__global__ void k_ct_part(const float* __restrict__ enc, const float* __restrict__ mask,
                          const float* __restrict__ cov, float* __restrict__ out,
                          long long out_size) {
    int b = blockIdx.x, q = blockIdx.y;
    int t = threadIdx.x; // 512
    __shared__ float at[512];
    __shared__ float red[32];
    float sc = (t < TKq) ? g_scores[b * TKq + t] : -F_INF;
    float mx = blockReduceMax(sc, red);
    float ex = 0.0f;
    if (t < TKq) ex = __expf(sc - mx) * mask[(size_t)b * TKq + t];
    float sum = blockReduceSum(ex, red);
    float a = ex / sum;
    at[t] = a;
    if (q == 0 && t < TKq) {
        g_attn[(size_t)b * TKq + t] = a;
        long long ia = OFF_ATTN + (long long)b * TKq + t;
        if (ia < out_size) out[ia] = a;
        long long icov = OFF_COV + (long long)b * TKq + t;
        if (icov < out_size) out[icov] = cov[(size_t)b * TKq + t] + a;
    }
    __syncthreads();
    const float* e = enc + ((size_t)b * TKq + q * 100) * NN + t;
    float acc = 0.0f;
    #pragma unroll 1
    for (int g = 0; g < 10; g++) {
        float ev[10];
        #pragma unroll
        for (int u = 0; u < 10; u++)
            ev[u] = e[(size_t)(g * 10 + u) * NN];   // 10 outstanding LDGs
        #pragma unroll
        for (int u = 0; u < 10; u++)
            acc = fmaf(at[q * 100 + g * 10 + u], ev[u], acc);
    }
    g_ctp[((b << 2) + q) * NN + t] = acc;
}

// ---------------- K7: combine c_t + p_gen ----------------
__global__ void k_ct_pgen(const float* __restrict__ Wpg, const float* __restrict__ bpg,
                          float* __restrict__ out, long long out_size) {
    int b = blockIdx.x;
    int n = threadIdx.x; // 512
    __shared__ float cts[NN];
    __shared__ float red[32];
    float v = g_ctp[((b << 2) + 0) * NN + n] + g_ctp[((b << 2) + 1) * NN + n]
            + g_ctp[((b << 2) + 2) * NN + n] + g_ctp[((b << 2) + 3) * NN + n];
    g_ct[(size_t)b * NN + n] = v;
    long long ic = OFF_CT + (long long)b * NN + n;
    if (ic < out_size) out[ic] = v;
    cts[n] = v;
    __syncthreads();
    float acc = 0.0f;
    for (int j = n; j < 1152; j += 512) {
        float x;
        if (j < 512)       x = cts[j];
        else if (j < 768)  x = g_h1[(size_t)b * Hh + (j - 512)];
        else if (j < 1024) x = g_c1[(size_t)b * Hh + (j - 768)];
        else               x = g_x[(size_t)b * EMBq + (j - 1024)];
        acc = fmaf(x, Wpg[j], acc);
    }
    acc = blockReduceSum(acc, red);
    if (n == 0) {
        float p = sigmoidf_(acc + bpg[0]);
        g_pgen[b] = p;
        long long ip = OFF_PGEN + b;
        if (ip < out_size) out[ip] = p;
    }
}

// ================= fp16 mma m16n8k16 logits GEMM (cp.async dbuf, online stats) =================
#define AROWU 36                      // u32 per smem row
#define STGU  (2 * 128 * AROWU)       // u32 per stage (A+B)
#define LOGITS_SMEM (2 * STGU * 4)    // 73728 bytes

__device__ __forceinline__ void mma_f16(float* c, const uint32_t* a, const uint32_t* b) {
    asm volatile(
        "mma.sync.aligned.m16n8k16.row.col.f32.f16.f16.f32 "
        "{%0,%1,%2,%3}, {%4,%5,%6,%7}, {%8,%9}, {%0,%1,%2,%3};"
        : "+f"(c[0]), "+f"(c[1]), "+f"(c[2]), "+f"(c[3])
        : "r"(a[0]), "r"(a[1]), "r"(a[2]), "r"(a[3]), "r"(b[0]), "r"(b[1]));
}
__device__ __forceinline__ void ldsm_x4(uint32_t* r, uint32_t saddr) {
    asm volatile("ldmatrix.sync.aligned.m8n8.x4.shared.b16 {%0,%1,%2,%3}, [%4];"
        : "=r"(r[0]), "=r"(r[1]), "=r"(r[2]), "=r"(r[3]) : "r"(saddr));
}
__device__ __forceinline__ void ldsm_x2(uint32_t* r, uint32_t saddr) {
    asm volatile("ldmatrix.sync.aligned.m8n8.x2.shared.b16 {%0,%1}, [%2];"
        : "=r"(r[0]), "=r"(r[1]) : "r"(saddr));
}

__global__ __launch_bounds__(256) void k_logits_h(const float* __restrict__ b2v) {
    extern __shared__ uint32_t smu[];
    __shared__ float st_m[128][4];
    __shared__ float st_s[128][4];
    uint32_t base = smem_u32(smu);

    int tid = threadIdx.x;
    int lane = tid & 31, wid = tid >> 5;
    int gid = lane >> 2, tig = lane & 3;
    int n0 = blockIdx.x * 128;
    int m0w = (wid >> 2) * 64;
    int n0w = (wid & 3) * 32;

    int aRow  = lane & 15;
    int aColB = ((lane >> 4) << 3) * 2;
    int bRow  = lane & 7;
    int bColB = ((lane >> 3) & 1) * 16;

    float acc[4][4][4];
    #pragma unroll
    for (int i = 0; i < 4; i++)
        #pragma unroll
        for (int j = 0; j < 4; j++)
            #pragma unroll
            for (int q = 0; q < 4; q++) acc[i][j][q] = 0.0f;

    #define PREF(kc, s) do {                                                      \
        int kkh = (kc) * 64;                                                      \
        uint32_t ab = base + (uint32_t)(s) * STGU * 4u;                           \
        uint32_t bb = ab + 128u * AROWU * 4u;                                     \
        _Pragma("unroll")                                                         \
        for (int it = 0; it < 4; it++) {                                          \
            int idx = tid + it * 256;                                             \
            int row = idx >> 3;                                                   \
            int q   = idx & 7;                                                    \
            const void* sa = (const void*)(g_out1h + (size_t)row * Hh + kkh + q * 8); \
            asm volatile("cp.async.ca.shared.global [%0], [%1], 16;"              \
                :: "r"(ab + (uint32_t)(row * 144 + q * 16)), "l"(sa));            \
            int gn = n0 + row;                                                    \
            int nc = (gn < Vq) ? gn : (Vq - 1);                                   \
            const void* sb = (const void*)(g_w2h + (size_t)nc * Hh + kkh + q * 8);\
            asm volatile("cp.async.ca.shared.global [%0], [%1], 16;"              \
                :: "r"(bb + (uint32_t)(row * 144 + q * 16)), "l"(sb));            \
        }                                                                         \
        asm volatile("cp.async.commit_group;");                                   \
    } while (0)

    PREF(0, 0);
    #pragma unroll 1
    for (int kc = 0; kc < 4; kc++) {
        if (kc < 3) {
            PREF(kc + 1, (kc + 1) & 1);
            asm volatile("cp.async.wait_group 1;");
        } else {
            asm volatile("cp.async.wait_group 0;");
        }
        __syncthreads();
        uint32_t asBase = base + (uint32_t)(kc & 1) * STGU * 4u;
        uint32_t bsBase = asBase + 128u * AROWU * 4u;
        #pragma unroll
        for (int ks = 0; ks < 4; ks++) {
            int koB = ks * 32;
            uint32_t a[4][4], b[4][2];
            #pragma unroll
            for (int i = 0; i < 4; i++)
                ldsm_x4(a[i], asBase + (uint32_t)((m0w + i * 16 + aRow) * 144 + koB + aColB));
            #pragma unroll
            for (int j = 0; j < 4; j++)
                ldsm_x2(b[j], bsBase + (uint32_t)((n0w + j * 8 + bRow) * 144 + koB + bColB));
            #pragma unroll
            for (int i = 0; i < 4; i++)
                #pragma unroll
                for (int j = 0; j < 4; j++) mma_f16(acc[i][j], a[i], b[j]);
        }
        __syncthreads();
    }
    #undef PREF

    // epilogue: bias + store logits + per-(row,tile) online softmax partials
    float rm[4][2], rs[4][2];
    #pragma unroll
    for (int i = 0; i < 4; i++) { rm[i][0] = rm[i][1] = NEG_BIG; rs[i][0] = rs[i][1] = 0.f; }

    #pragma unroll
    for (int j = 0; j < 4; j++) {
        int col = n0 + n0w + j * 8 + tig * 2;
        bool valid = (col < Vq);
        float bx0 = 0.f, bx1 = 0.f;
        if (valid) { bx0 = b2v[col]; bx1 = b2v[col + 1]; }
        #pragma unroll
        for (int i = 0; i < 4; i++) {
            float v0 = acc[i][j][0] + bx0, v1 = acc[i][j][1] + bx1;
            float v2 = acc[i][j][2] + bx0, v3 = acc[i][j][3] + bx1;
            if (valid) {
                int r0 = m0w + i * 16 + gid;
                *(float2*)(g_logits + (size_t)r0 * Vq + col) = make_float2(v0, v1);
                *(float2*)(g_logits + (size_t)(r0 + 8) * Vq + col) = make_float2(v2, v3);
                float mp = fmaxf(v0, v1);
                float sp = __expf(v0 - mp) + __expf(v1 - mp);
                float mn = fmaxf(rm[i][0], mp);
                rs[i][0] = rs[i][0] * __expf(rm[i][0] - mn) + sp * __expf(mp - mn);
                rm[i][0] = mn;
                mp = fmaxf(v2, v3);
                sp = __expf(v2 - mp) + __expf(v3 - mp);
                mn = fmaxf(rm[i][1], mp);
                rs[i][1] = rs[i][1] * __expf(rm[i][1] - mn) + sp * __expf(mp - mn);
                rm[i][1] = mn;
            }
        }
    }
    #pragma unroll
    for (int i = 0; i < 4; i++) {
        #pragma unroll
        for (int hf = 0; hf < 2; hf++) {
            float m = rm[i][hf], s = rs[i][hf];
            #pragma unroll
            for (int o = 1; o <= 2; o <<= 1) {
                float m2 = __shfl_xor_sync(0xffffffffu, m, o);
                float s2 = __shfl_xor_sync(0xffffffffu, s, o);
                float mn = fmaxf(m, m2);
                s = s * __expf(m - mn) + s2 * __expf(m2 - mn);
                m = mn;
            }
            rm[i][hf] = m; rs[i][hf] = s;
        }
    }
    int wn = wid & 3;
    if (tig == 0) {
        #pragma unroll
        for (int i = 0; i < 4; i++) {
            #pragma unroll
            for (int hf = 0; hf < 2; hf++) {
                int row = m0w + i * 16 + gid + hf * 8;
                st_m[row][wn] = rm[i][hf];
                st_s[row][wn] = rs[i][hf];
            }
        }
    }
    __syncthreads();
    if (tid < 128) {
        float M = st_m[tid][0], S = st_s[tid][0];
        #pragma unroll
        for (int i = 1; i < 4; i++) {
            float m2 = st_m[tid][i], s2 = st_s[tid][i];
            float mn = fmaxf(M, m2);
            S = S * __expf(M - mn) + s2 * __expf(m2 - mn);
            M = mn;
        }
        g_pm[(size_t)tid * NT + blockIdx.x] = M;
        g_ps[(size_t)tid * NT + blockIdx.x] = S;
    }
}

// ---------------- merge per-tile stats -> per-row (M, S) ----------------
__global__ void k_vmerge() {
    int b = blockIdx.x;
    int tid = threadIdx.x; // 128
    float m = NEG_BIG, s = 0.0f;
    for (int t = tid; t < NT; t += 128) {
        float m2 = g_pm[(size_t)b * NT + t], s2 = g_ps[(size_t)b * NT + t];
        float mn = fmaxf(m, m2);
        s = s * __expf(m - mn) + s2 * __expf(m2 - mn);
        m = mn;
    }
    #pragma unroll
    for (int o = 16; o; o >>= 1) {
        float m2 = __shfl_xor_sync(0xffffffffu, m, o);
        float s2 = __shfl_xor_sync(0xffffffffu, s, o);
        float mn = fmaxf(m, m2);
        s = s * __expf(m - mn) + s2 * __expf(m2 - mn);
        m = mn;
    }
    __shared__ float sm_[4], ss_[4];
    int w = tid >> 5, l = tid & 31;
    if (l == 0) { sm_[w] = m; ss_[w] = s; }
    __syncthreads();
    if (tid == 0) {
        float M = sm_[0], S = ss_[0];
        #pragma unroll
        for (int i = 1; i < 4; i++) {
            float mn = fmaxf(M, sm_[i]);
            S = S * __expf(M - mn) + ss_[i] * __expf(sm_[i] - mn);
            M = mn;
        }
        g_rmax[b] = M;
        g_rsum[b] = S;
    }
}

// ---------------- final dist base ----------------
__global__ void k_final(float* __restrict__ out, long long out_size) {
    int v = blockIdx.x * blockDim.x + threadIdx.x;
    int b = blockIdx.y;
    if (v >= VXq) return;
    float val = 0.0f;
    if (v < Vq)
        val = g_pgen[b] * __expf(g_logits[(size_t)b * Vq + v] - g_rmax[b]) / g_rsum[b];
    long long idx = OFF_FINAL + (long long)b * VXq + v;
    if (idx < out_size) out[idx] = val;
}

// ---------------- copy scatter-add ----------------
__global__ void k_scatter(const int* __restrict__ ebev, float* __restrict__ out,
                          long long out_size) {
    int i = blockIdx.x * blockDim.x + threadIdx.x;
    if (i >= Bq * TKq) return;
    int b = i / TKq;
    float add = (1.0f - g_pgen[b]) * g_attn[i];
    int tgt = ebev[i];
    long long idx = OFF_FINAL + (long long)b * VXq + tgt;
    if (idx < out_size && tgt >= 0 && tgt < VXq) atomicAdd(&out[idx], add);
}

// ---------------- launch ----------------
extern "C" void kernel_launch(void* const* d_in, const int* in_sizes, int n_in,
                              void* d_out, int out_size) {
    const int*   y        = (const int*)  d_in[0];
    const float* s_h      = (const float*)d_in[1];
    const float* s_c      = (const float*)d_in[2];
    const float* enc_out  = (const float*)d_in[3];
    const float* enc_feat = (const float*)d_in[4];
    const float* mask     = (const float*)d_in[5];
    const float* ct1      = (const float*)d_in[6];
    const int*   ebev     = (const int*)  d_in[8];
    const float* cov      = (const float*)d_in[9];
    const float* emb      = (const float*)d_in[11];
    const float* Wx       = (const float*)d_in[12];
    const float* bx       = (const float*)d_in[13];
    const float* w_ih     = (const float*)d_in[14];
    const float* b_ih     = (const float*)d_in[15];
    const float* w_hh     = (const float*)d_in[16];
    const float* b_hh     = (const float*)d_in[17];
    const float* Wp       = (const float*)d_in[18];
    const float* bp       = (const float*)d_in[19];
    const float* v_w      = (const float*)d_in[20];
    const float* Wc       = (const float*)d_in[21];
    const float* Wpg      = (const float*)d_in[22];
    const float* bpg      = (const float*)d_in[23];
    const float* W1       = (const float*)d_in[24];
    const float* b1       = (const float*)d_in[25];
    const float* W2       = (const float*)d_in[26];
    const float* b2       = (const float*)d_in[27];
    float* out = (float*)d_out;
    long long osz = (long long)out_size;

    float*  pg_h1;     cudaGetSymbolAddress((void**)&pg_h1, g_h1);
    float*  pg_c1;     cudaGetSymbolAddress((void**)&pg_c1, g_c1);
    float*  pg_decfea; cudaGetSymbolAddress((void**)&pg_decfea, g_decfea);
    float*  pg_ct;     cudaGetSymbolAddress((void**)&pg_ct, g_ct);
    float*  pg_out1;   cudaGetSymbolAddress((void**)&pg_out1, g_out1);
    __half* pg_out1h;  cudaGetSymbolAddress((void**)&pg_out1h, g_out1h);

    static int attr_set = 0;
    if (!attr_set) {
        cudaFuncSetAttribute(k_logits_h, cudaFuncAttributeMaxDynamicSharedMemorySize,
                             LOGITS_SMEM);
        attr_set = 1;
    }

    // single-stream chain (streams measured as a regression in R16)
    k_xgemm<<<dim3(EMBq / 32, 2), 256>>>(y, ct1, emb, Wx, bx);
    k_gates_lstm<<<dim3(Hh / 32, 4), 256>>>(s_h, s_c, w_ih, b_ih, w_hh, b_hh, out, osz);
    gemm_seg<<<dim3(NN / 32, 2), 256>>>(pg_h1, Hh, Wp, NN,
                                        pg_c1, Hh, Wp + Hh, NN,
                                        Hh, Hh, bp, pg_decfea, (__half*)nullptr, NN);
    k_scores<<<(Bq * TKq) / 8, 256>>>(enc_feat, cov, Wc, v_w);
    k_w2h<<<((size_t)Vq * Hh / 4 + 255) / 256, 256>>>(W2);
    k_ct_part<<<dim3(Bq, 4), 512>>>(enc_out, mask, cov, out, osz);
    k_ct_pgen<<<Bq, 512>>>(Wpg, bpg, out, osz);
    gemm_seg<<<dim3(Hh / 32, 2), 256>>>(pg_h1, Hh, W1, Hh + NN,
                                        pg_ct, NN, W1 + Hh, Hh + NN,
                                        Hh, NN, b1, pg_out1, pg_out1h, Hh);
    k_logits_h<<<NT, 256, LOGITS_SMEM>>>(b2);
    k_vmerge<<<Bq, 128>>>();
    dim3 gf((VXq + 511) / 512, Bq);
    k_final<<<gf, 512>>>(out, osz);
    k_scatter<<<(Bq * TKq + 255) / 256, 256>>>(ebev, out, osz);
}